// round 2
// baseline (speedup 1.0000x reference)
#include <cuda_runtime.h>
#include <cuda_bf16.h>

#define NN 50000
#define EE 800000
#define DD 64
#define LN_EPS 1e-5f

// Persistent scratch (no allocations allowed in kernel_launch)
__device__ float  g_h[NN * DD];      // h = x @ W
__device__ float  g_deg[NN];         // degree (init 1.0 for self loop)
__device__ float  g_dinv[NN];        // deg^{-1/2}
__device__ double g_stats[2];        // {sum, sumsq}

// ---------------------------------------------------------------------------
// 0) zero output accumulator, init degrees to 1 (self-loop weight), zero stats
// ---------------------------------------------------------------------------
__global__ void k_zero(float* __restrict__ out, int n_out, int n_nodes) {
    int i = blockIdx.x * blockDim.x + threadIdx.x;
    if (i < n_out)   out[i] = 0.0f;
    if (i < n_nodes) g_deg[i] = 1.0f;
    if (i == 0) { g_stats[0] = 0.0; g_stats[1] = 0.0; }
}

// ---------------------------------------------------------------------------
// 1) h = x @ W   (W: [64,64] row-major, out feature is fastest dim)
//    16 rows per block, 256 threads: thread (r0,d) computes rows r0+4j, col d
// ---------------------------------------------------------------------------
__global__ void k_gemm(const float* __restrict__ x, const float* __restrict__ W,
                       int n) {
    __shared__ float Ws[DD * DD];
    __shared__ float xs[16 * DD];
    for (int i = threadIdx.x; i < DD * DD; i += 256) Ws[i] = W[i];

    int base = blockIdx.x * 16;
    for (int i = threadIdx.x; i < 16 * DD; i += 256) {
        int row = base + (i >> 6);
        xs[i] = (row < n) ? x[row * DD + (i & 63)] : 0.0f;
    }
    __syncthreads();

    int r0 = threadIdx.x >> 6;   // 0..3
    int d  = threadIdx.x & 63;
    float acc0 = 0.f, acc1 = 0.f, acc2 = 0.f, acc3 = 0.f;
#pragma unroll
    for (int k = 0; k < DD; k++) {
        float wv = Ws[k * DD + d];
        acc0 += xs[(r0     ) * DD + k] * wv;
        acc1 += xs[(r0 +  4) * DD + k] * wv;
        acc2 += xs[(r0 +  8) * DD + k] * wv;
        acc3 += xs[(r0 + 12) * DD + k] * wv;
    }
    int row = base + r0;
    if (row      < n) g_h[(row     ) * DD + d] = acc0;
    if (row +  4 < n) g_h[(row +  4) * DD + d] = acc1;
    if (row +  8 < n) g_h[(row +  8) * DD + d] = acc2;
    if (row + 12 < n) g_h[(row + 12) * DD + d] = acc3;
}

// ---------------------------------------------------------------------------
// 2) deg[col] += w  (self loops already baked in as init 1.0)
// ---------------------------------------------------------------------------
__global__ void k_deg(const int* __restrict__ ei,
                      const float* __restrict__ ew, int E) {
    int e = blockIdx.x * blockDim.x + threadIdx.x;
    if (e < E) {
        int c = ei[E + e];   // edge_index[1] = targets
        atomicAdd(&g_deg[c], ew[e]);
    }
}

// ---------------------------------------------------------------------------
// 3) dinv = rsqrt(deg)   (deg >= 1 always, so the deg>0 branch is moot)
// ---------------------------------------------------------------------------
__global__ void k_dinv(int n) {
    int i = blockIdx.x * blockDim.x + threadIdx.x;
    if (i < n) g_dinv[i] = rsqrtf(g_deg[i]);
}

// ---------------------------------------------------------------------------
// 4) scatter: out[col] += h[row] * (dinv[row]*w*dinv[col])
//    16 threads per edge, each handles a float4 via red.global.add.v4.f32
// ---------------------------------------------------------------------------
__global__ void k_scat(const int* __restrict__ ei,
                       const float* __restrict__ ew,
                       float* __restrict__ out, int E) {
    int t = blockIdx.x * blockDim.x + threadIdx.x;
    int e = t >> 4;
    if (e >= E) return;
    int seg = t & 15;
    int r = ei[e];
    int c = ei[E + e];
    float nrm = g_dinv[r] * ew[e] * g_dinv[c];
    const float4 hv = *reinterpret_cast<const float4*>(g_h + r * DD + seg * 4);
    float* p = out + c * DD + seg * 4;
    asm volatile("red.global.add.v4.f32 [%0], {%1, %2, %3, %4};"
                 :: "l"(p), "f"(hv.x * nrm), "f"(hv.y * nrm),
                    "f"(hv.z * nrm), "f"(hv.w * nrm)
                 : "memory");
}

// ---------------------------------------------------------------------------
// 5) add self-loop contribution + bias, accumulate global sum/sumsq
//    one float4 per thread (nq = N*16 threads)
// ---------------------------------------------------------------------------
__global__ void k_stats(float* __restrict__ out, const float* __restrict__ b,
                        int nq) {
    int t = blockIdx.x * blockDim.x + threadIdx.x;
    float s = 0.f, sq = 0.f;
    if (t < nq) {
        int node = t >> 4, seg = t & 15;
        float4 a = *reinterpret_cast<float4*>(out + node * DD + seg * 4);
        const float4 hv = *reinterpret_cast<const float4*>(g_h + node * DD + seg * 4);
        const float4 bv = *reinterpret_cast<const float4*>(b + seg * 4);
        float di = g_dinv[node];
        float sn = di * di;                 // self-loop norm = 1/deg
        a.x += hv.x * sn + bv.x;
        a.y += hv.y * sn + bv.y;
        a.z += hv.z * sn + bv.z;
        a.w += hv.w * sn + bv.w;
        *reinterpret_cast<float4*>(out + node * DD + seg * 4) = a;
        s  = a.x + a.y + a.z + a.w;
        sq = a.x * a.x + a.y * a.y + a.z * a.z + a.w * a.w;
    }
    double ds = (double)s, dq = (double)sq;
#pragma unroll
    for (int o = 16; o; o >>= 1) {
        ds += __shfl_down_sync(0xffffffffu, ds, o);
        dq += __shfl_down_sync(0xffffffffu, dq, o);
    }
    __shared__ double sh[16];
    int w = threadIdx.x >> 5, l = threadIdx.x & 31;
    if (l == 0) { sh[w] = ds; sh[8 + w] = dq; }
    __syncthreads();
    if (threadIdx.x == 0) {
        double S = 0.0, Q = 0.0;
#pragma unroll
        for (int i = 0; i < 8; i++) { S += sh[i]; Q += sh[8 + i]; }
        atomicAdd(&g_stats[0], S);
        atomicAdd(&g_stats[1], Q);
    }
}

// ---------------------------------------------------------------------------
// 6) layernorm (graph mode: global mean/std) + affine + relu
// ---------------------------------------------------------------------------
__global__ void k_norm(float* __restrict__ out,
                       const float* __restrict__ lnw,
                       const float* __restrict__ lnb, int nq, int total) {
    int t = blockIdx.x * blockDim.x + threadIdx.x;
    if (t >= nq) return;
    double S = g_stats[0], Q = g_stats[1];
    float mean = (float)(S / (double)total);
    float var  = (float)(Q / (double)total - (S / (double)total) * (S / (double)total));
    var = var > 0.f ? var : 0.f;
    float istd = 1.0f / (sqrtf(var) + LN_EPS);
    int seg = t & 15;
    float4 v  = reinterpret_cast<float4*>(out)[t];
    const float4 wv = *reinterpret_cast<const float4*>(lnw + seg * 4);
    const float4 bv = *reinterpret_cast<const float4*>(lnb + seg * 4);
    v.x = fmaxf((v.x - mean) * istd * wv.x + bv.x, 0.f);
    v.y = fmaxf((v.y - mean) * istd * wv.y + bv.y, 0.f);
    v.z = fmaxf((v.z - mean) * istd * wv.z + bv.z, 0.f);
    v.w = fmaxf((v.w - mean) * istd * wv.w + bv.w, 0.f);
    reinterpret_cast<float4*>(out)[t] = v;
}

// ---------------------------------------------------------------------------
extern "C" void kernel_launch(void* const* d_in, const int* in_sizes, int n_in,
                              void* d_out, int out_size) {
    const float* x   = (const float*)d_in[0];
    const float* ew  = (const float*)d_in[1];
    const float* W   = (const float*)d_in[2];
    const float* b   = (const float*)d_in[3];
    const float* lnw = (const float*)d_in[4];
    const float* lnb = (const float*)d_in[5];
    const int*   ei  = (const int*)d_in[6];

    int N = in_sizes[0] / DD;
    int E = in_sizes[1];
    float* out = (float*)d_out;

    int nq = N * (DD / 4);   // float4 count

    k_zero <<<(N * DD + 255) / 256, 256>>>(out, N * DD, N);
    k_gemm <<<(N + 15) / 16, 256>>>(x, W, N);
    k_deg  <<<(E + 255) / 256, 256>>>(ei, ew, E);
    k_dinv <<<(N + 255) / 256, 256>>>(N);
    k_scat <<<((long long)E * 16 + 255) / 256, 256>>>(ei, ew, out, E);
    k_stats<<<(nq + 255) / 256, 256>>>(out, b, nq);
    k_norm <<<(nq + 255) / 256, 256>>>(out, lnw, lnb, nq, N * DD);
}